// round 10
// baseline (speedup 1.0000x reference)
#include <cuda_runtime.h>
#include <cuda_bf16.h>
#include <math.h>
#include <stdint.h>

#define T_LEN 8192
#define HALF  4096
#define CH    128
#define BATCH 16
#define NSIG  (BATCH * CH)

#define KSPLIT 8
#define KC    64                           // int8 K per chunk (64 bytes)
#define NCHUNK (T_LEN / KSPLIT / KC)       // 16
#define ROWB  80                           // 64B data + 16B pad per row
#define AHOFF 0
#define ALOFF (128 * ROWB)                 // 10240
#define BHOFF (2 * 128 * ROWB)             // 20480
#define BLOFF (BHOFF + 64 * ROWB)          // 25600
#define BUFB  (BLOFF + 64 * ROWB)          // 30720 bytes per buffer

// Scratch (alloc-free rule: __device__ globals)
__device__ int8_t g_h[(size_t)BATCH * 256 * T_LEN];           // hi int8: 32 MB
__device__ int8_t g_l[(size_t)BATCH * 256 * T_LEN];           // lo int8: 32 MB
__device__ int2   g_gram[(size_t)KSPLIT * BATCH * 3 * CH * CH]; // (hh,xx): 50 MB

// ===========================================================================
// PTX helpers (sm_103 family-portable: ldmatrix / mma.sync / cp.async)
// ===========================================================================
__device__ __forceinline__ uint32_t smem_u32(const void* p) {
    uint32_t a;
    asm("{ .reg .u64 t; cvta.to.shared.u64 t, %1; cvt.u32.u64 %0, t; }"
        : "=r"(a) : "l"(p));
    return a;
}
__device__ __forceinline__ void ldsm4(uint32_t* d, uint32_t addr) {
    asm volatile("ldmatrix.sync.aligned.m8n8.x4.shared.b16 {%0,%1,%2,%3}, [%4];"
                 : "=r"(d[0]), "=r"(d[1]), "=r"(d[2]), "=r"(d[3]) : "r"(addr));
}
__device__ __forceinline__ void ldsm2(uint32_t* d, uint32_t addr) {
    asm volatile("ldmatrix.sync.aligned.m8n8.x2.shared.b16 {%0,%1}, [%2];"
                 : "=r"(d[0]), "=r"(d[1]) : "r"(addr));
}
__device__ __forceinline__ void mma_s8(int* d, const uint32_t* a, const uint32_t* b) {
    asm volatile(
        "mma.sync.aligned.m16n8k32.row.col.s32.s8.s8.s32 "
        "{%0,%1,%2,%3}, {%4,%5,%6,%7}, {%8,%9}, {%0,%1,%2,%3};"
        : "+r"(d[0]), "+r"(d[1]), "+r"(d[2]), "+r"(d[3])
        : "r"(a[0]), "r"(a[1]), "r"(a[2]), "r"(a[3]), "r"(b[0]), "r"(b[1]));
}
__device__ __forceinline__ void cp16(uint32_t smem, const void* g) {
    asm volatile("cp.async.cg.shared.global [%0], [%1], 16;"
                 :: "r"(smem), "l"(g) : "memory");
}
#define CP_COMMIT() asm volatile("cp.async.commit_group;" ::: "memory")
#define CP_WAIT1()  asm volatile("cp.async.wait_group 1;" ::: "memory")
#define CP_WAIT0()  asm volatile("cp.async.wait_group 0;" ::: "memory")

// ===========================================================================
// Kernel 1: register-resident FFT (R9 body), int8 h/l packed epilogue.
// ===========================================================================
__device__ __forceinline__ int swz(int i) { return i ^ ((i >> 5) & 31); }

template<int P, int LB, int FWD>
__device__ __forceinline__ void stage_one(float2 v[16], int base,
                                          const float2* __restrict__ tw) {
    const int s  = P + LB;
    const int bm = base & ((1 << s) - 1);
    float2 wc[(LB < 3) ? (1 << LB) : 1];
    if (LB < 3) {
#pragma unroll
        for (int q = 0; q < (1 << LB); q++)
            wc[q] = tw[(bm + (q << P)) << (12 - s)];
    }
#pragma unroll
    for (int rr = 0; rr < 16; rr++) {
        if ((rr >> LB) & 1) continue;
        const int r1 = rr | (1 << LB);
        float2 w;
        if (LB < 3) w = wc[rr & ((1 << LB) - 1)];
        else        w = tw[(bm + ((rr & 7) << P)) << (12 - s)];
        float2 a = v[rr], b = v[r1];
        if (FWD) {
            v[rr] = make_float2(a.x + b.x, a.y + b.y);
            float2 d = make_float2(a.x - b.x, a.y - b.y);
            v[r1] = make_float2(d.x * w.x - d.y * w.y, d.x * w.y + d.y * w.x);
        } else {
            float2 tt = make_float2(b.x * w.x + b.y * w.y, b.y * w.x - b.x * w.y);
            v[rr] = make_float2(a.x + tt.x, a.y + tt.y);
            v[r1] = make_float2(a.x - tt.x, a.y - tt.y);
        }
    }
}

template<int P, int FWD, int LBLO, int LBHI>
__device__ __forceinline__ void stages(float2 v[16], int base,
                                       const float2* __restrict__ tw) {
    if (FWD) {
        if (LBHI >= 3 && 3 >= LBLO) stage_one<P, 3, 1>(v, base, tw);
        if (LBHI >= 2 && 2 >= LBLO) stage_one<P, 2, 1>(v, base, tw);
        if (LBHI >= 1 && 1 >= LBLO) stage_one<P, 1, 1>(v, base, tw);
        if (LBHI >= 0 && 0 >= LBLO) stage_one<P, 0, 1>(v, base, tw);
    } else {
        if (LBLO <= 0 && 0 <= LBHI) stage_one<P, 0, 0>(v, base, tw);
        if (LBLO <= 1 && 1 <= LBHI) stage_one<P, 1, 0>(v, base, tw);
        if (LBLO <= 2 && 2 <= LBHI) stage_one<P, 2, 0>(v, base, tw);
        if (LBLO <= 3 && 3 <= LBHI) stage_one<P, 3, 0>(v, base, tw);
    }
}

extern __shared__ float2 smm[];   // [0..8191]=exchange, [8192..12287]=twiddles

template<int K>
__device__ __forceinline__ uint32_t pick4(uint4 w) {
    const uint32_t s = (uint32_t)K | ((uint32_t)(K + 4) << 4);
    return __byte_perm(__byte_perm(w.x, w.y, s), __byte_perm(w.z, w.w, s), 0x5410);
}

__global__ void __launch_bounds__(512) fft_kernel(const float* __restrict__ x) {
    float2* sm = smm;
    float2* tw = smm + T_LEN;
    const int tid = threadIdx.x;
    const long long gbase = (long long)blockIdx.x * T_LEN;

    for (int t = tid; t < HALF; t += 512) {
        float s, c;
        sincosf(-6.283185307179586e0f * (float)t / (float)T_LEN, &s, &c);
        tw[t] = make_float2(c, s);
    }

    const int baseA = tid;                                  // P=9
    const int baseB = ((tid >> 5) << 9) + (tid & 31);       // P=5
    const int baseC = ((tid >> 1) << 5) + (tid & 1);        // P=1
    const int baseD = tid << 4;                             // P=0
    const int baseE = ((tid >> 4) << 8) + (tid & 15);       // P=4
    const int baseF = ((tid >> 8) << 12) + (tid & 255);     // P=8

    float2 v[16];
#pragma unroll
    for (int r = 0; r < 16; r++)
        v[r] = make_float2(x[gbase + tid + r * 512], 0.0f);
    __syncthreads();

    stages<9, 1, 0, 3>(v, baseA, tw);
#pragma unroll
    for (int r = 0; r < 16; r++) sm[swz(baseA + (r << 9))] = v[r];
    __syncthreads();
#pragma unroll
    for (int r = 0; r < 16; r++) v[r] = sm[swz(baseB + (r << 5))];
    __syncthreads();

    stages<5, 1, 0, 3>(v, baseB, tw);
#pragma unroll
    for (int r = 0; r < 16; r++) sm[swz(baseB + (r << 5))] = v[r];
    __syncthreads();
#pragma unroll
    for (int r = 0; r < 16; r++) v[r] = sm[swz(baseC + (r << 1))];
    __syncthreads();

    stages<1, 1, 0, 3>(v, baseC, tw);
#pragma unroll
    for (int r = 0; r < 16; r++) sm[swz(baseC + (r << 1))] = v[r];
    __syncthreads();
#pragma unroll
    for (int r = 0; r < 16; r++) v[r] = sm[swz(baseD + r)];
    __syncthreads();

#pragma unroll
    for (int r = 0; r < 16; r += 2) {
        float2 s0 = make_float2(v[r].x + v[r + 1].x, v[r].y + v[r + 1].y);
        v[r] = s0; v[r + 1] = s0;
    }

    stages<0, 0, 1, 3>(v, baseD, tw);
#pragma unroll
    for (int r = 0; r < 16; r++) sm[swz(baseD + r)] = v[r];
    __syncthreads();
#pragma unroll
    for (int r = 0; r < 16; r++) v[r] = sm[swz(baseE + (r << 4))];
    __syncthreads();

    stages<4, 0, 0, 3>(v, baseE, tw);
#pragma unroll
    for (int r = 0; r < 16; r++) sm[swz(baseE + (r << 4))] = v[r];
    __syncthreads();
#pragma unroll
    for (int r = 0; r < 16; r++) v[r] = sm[swz(baseF + (r << 8))];
    __syncthreads();

    stages<8, 0, 0, 3>(v, baseF, tw);
#pragma unroll
    for (int r = 0; r < 16; r++) sm[swz(baseF + (r << 8))] = v[r];
    __syncthreads();
#pragma unroll
    for (int r = 0; r < 16; r++) v[r] = sm[swz(baseA + (r << 9))];
    __syncthreads();

    stages<9, 0, 3, 3>(v, baseA, tw);

    // ---- epilogue: normalize, int8 h/l quantize, pack 4 bytes per t ----
    uint32_t* sbW = (uint32_t*)sm;   // word per t: b0=ch b1=cl b2=sh b3=sl
#pragma unroll
    for (int r = 0; r < 16; r++) {
        const int t = tid + r * 512;
        float2 u = v[r];
        float m2 = u.x * u.x + u.y * u.y;
        float cx, sx;
        if (m2 > 0.0f) {
            float inv = rsqrtf(m2);
            cx = u.x * inv; sx = u.y * inv;
        } else {
            cx = 1.0f; sx = 0.0f;
        }
        int chq = __float2int_rn(cx * 127.0f);
        float rc = fmaf((float)chq, -7.874015748031496e-3f, cx);
        int clq = __float2int_rn(rc * 32258.0f);
        int shq = __float2int_rn(sx * 127.0f);
        float rs = fmaf((float)shq, -7.874015748031496e-3f, sx);
        int slq = __float2int_rn(rs * 32258.0f);
        sbW[t] = (uint32_t)(chq & 0xFF)
               | ((uint32_t)(clq & 0xFF) << 8)
               | ((uint32_t)(shq & 0xFF) << 16)
               | ((uint32_t)(slq & 0xFF) << 24);
    }
    __syncthreads();

    const int bb = blockIdx.x >> 7;
    const int cc = blockIdx.x & 127;
    const size_t rowc = ((size_t)bb * 256 + cc) * T_LEN;
    const size_t rows = rowc + (size_t)128 * T_LEN;

    // Thread covers t in [16*tid, 16*tid+16): 4 uint4 words -> 4 byte-streams
    const uint4* S4 = (const uint4*)sbW;
    uint4 W0 = S4[4 * tid], W1 = S4[4 * tid + 1];
    uint4 W2 = S4[4 * tid + 2], W3 = S4[4 * tid + 3];

    uint4 o;
    o = make_uint4(pick4<0>(W0), pick4<0>(W1), pick4<0>(W2), pick4<0>(W3));
    ((uint4*)(g_h + rowc))[tid] = o;
    o = make_uint4(pick4<1>(W0), pick4<1>(W1), pick4<1>(W2), pick4<1>(W3));
    ((uint4*)(g_l + rowc))[tid] = o;
    o = make_uint4(pick4<2>(W0), pick4<2>(W1), pick4<2>(W2), pick4<2>(W3));
    ((uint4*)(g_h + rows))[tid] = o;
    o = make_uint4(pick4<3>(W0), pick4<3>(W1), pick4<3>(W2), pick4<3>(W3));
    ((uint4*)(g_l + rows))[tid] = o;
}

// ===========================================================================
// Kernel 2: int8 hi/lo-split Gram via mma.sync.m16n8k32.s8.
// CTA tile 128x64. blockIdx.y: q = y>>1 (0=CC,1=SS,2=SC), half = y&1.
// acc_hh = H.H^T ; acc_xx = H.L^T + L.H^T  (scale 1/(127*32258) applied later)
// Diagonal tiles (CC,SS): B aliases A's smem region (B rows subset of A).
// ===========================================================================
extern __shared__ __align__(128) char gsm[];   // 2 * BUFB = 61440

__global__ void __launch_bounds__(256, 2) gram_s8() {
    const int tid  = threadIdx.x;
    const int wid  = tid >> 5;
    const int lane = tid & 31;
    const int ks   = blockIdx.x;
    const int ty   = blockIdx.y;
    const int b    = blockIdx.z;
    const int q    = ty >> 1;                 // 0=CC 1=SS 2=SC
    const int half = ty & 1;                  // n half: cols 0-63 / 64-127
    const int ms   = (q == 0) ? 0 : 1;
    const int ns   = (q == 1) ? 1 : 0;
    const bool diag = (q < 2);

    const uint32_t sb = smem_u32(gsm);
    const size_t k0 = (size_t)ks * (T_LEN / KSPLIT);

    // ---- loader: 6 passes (4 if diag) x 64 rows, 4x16B quads per row ----
    const int sub = tid & 3;
    const int vrw = tid >> 2;                 // 0..63
    const int npass = diag ? 4 : 6;

    const int8_t* psrc[6]; uint32_t pdst[6];
#pragma unroll
    for (int p = 0; p < 6; p++) {
        int r, grow; const int8_t* srcArr; uint32_t mof;
        if (p < 4) {                          // A: h (p0,1) then l (p2,3)
            r = vrw + (p & 1) * 64;
            grow = b * 256 + ms * 128 + r;
            srcArr = (p < 2) ? g_h : g_l;
            mof = (p < 2) ? AHOFF : ALOFF;
        } else {                              // B: h (p4), l (p5)
            r = vrw;
            grow = b * 256 + ns * 128 + half * 64 + r;
            srcArr = (p == 4) ? g_h : g_l;
            mof = (p == 4) ? BHOFF : BLOFF;
        }
        psrc[p] = srcArr + (size_t)grow * T_LEN + k0 + sub * 16;
        pdst[p] = mof + (uint32_t)(r * ROWB + sub * 16);
    }

    auto load_chunk = [&](int c) {
        const uint32_t bufb = sb + (uint32_t)((c & 1) * BUFB);
        const int kofs = c * KC;
#pragma unroll
        for (int p = 0; p < 6; p++) {
            if (p >= npass) break;
            cp16(bufb + pdst[p], psrc[p] + kofs);
        }
        CP_COMMIT();
    };

    // ---- compute: 8 warps = 4m x 2n; warp tile 32x32 (mt2 x nt4) ----
    const int mrow0 = (wid >> 1) * 32;
    const int ncol0 = (wid & 1) * 32;
    const uint32_t bHbase = diag ? (uint32_t)(AHOFF + half * 64 * ROWB) : (uint32_t)BHOFF;
    const uint32_t bLbase = diag ? (uint32_t)(ALOFF + half * 64 * ROWB) : (uint32_t)BLOFF;

    int hh[2][4][4], xx[2][4][4];
#pragma unroll
    for (int mt = 0; mt < 2; mt++)
#pragma unroll
        for (int nt = 0; nt < 4; nt++)
#pragma unroll
            for (int e = 0; e < 4; e++) { hh[mt][nt][e] = 0; xx[mt][nt][e] = 0; }

    load_chunk(0);
    for (int c = 0; c < NCHUNK; c++) {
        if (c + 1 < NCHUNK) { load_chunk(c + 1); CP_WAIT1(); }
        else                { CP_WAIT0(); }
        __syncthreads();

        const uint32_t bufb = sb + (uint32_t)((c & 1) * BUFB);
#pragma unroll
        for (int kstep = 0; kstep < 2; kstep++) {
            const int kb = kstep * 32;
            uint32_t bh[4][2], bl[4][2];
            const int brow  = ncol0 + (lane & 7);
            const int bcolb = ((lane >> 3) & 1) * 16 + kb;
#pragma unroll
            for (int nt = 0; nt < 4; nt++) {
                const uint32_t bo = (uint32_t)((brow + nt * 8) * ROWB + bcolb);
                ldsm2(bh[nt], bufb + bHbase + bo);
                ldsm2(bl[nt], bufb + bLbase + bo);
            }
            const int arow  = mrow0 + (lane & 15);
            const int acolb = (lane >> 4) * 16 + kb;
#pragma unroll
            for (int mt = 0; mt < 2; mt++) {
                uint32_t ah[4], al[4];
                const uint32_t ao = (uint32_t)((arow + mt * 16) * ROWB + acolb);
                ldsm4(ah, bufb + AHOFF + ao);
                ldsm4(al, bufb + ALOFF + ao);
#pragma unroll
                for (int nt = 0; nt < 4; nt++) {
                    mma_s8(hh[mt][nt], ah, bh[nt]);
                    mma_s8(xx[mt][nt], ah, bl[nt]);
                    mma_s8(xx[mt][nt], al, bh[nt]);
                }
            }
        }
        __syncthreads();
    }

    // ---- epilogue: int4 stores of (hh,xx) pairs ----
    int2* __restrict__ G =
        g_gram + ((size_t)((ks * BATCH + b) * 3 + q)) * (CH * CH);
    const int r0 = lane >> 2;
    const int c0 = half * 64 + ncol0 + (lane & 3) * 2;
#pragma unroll
    for (int mt = 0; mt < 2; mt++) {
        const int row = mrow0 + mt * 16 + r0;
#pragma unroll
        for (int nt = 0; nt < 4; nt++) {
            const int col = c0 + nt * 8;
            *(int4*)(G + row * CH + col) =
                make_int4(hh[mt][nt][0], xx[mt][nt][0], hh[mt][nt][1], xx[mt][nt][1]);
            *(int4*)(G + (row + 8) * CH + col) =
                make_int4(hh[mt][nt][2], xx[mt][nt][2], hh[mt][nt][3], xx[mt][nt][3]);
        }
    }
}

// ===========================================================================
// Kernel 3: combine K-splits; Re = CC+SS, Im = SC_ij - SC_ji; PLV = |.|/T.
// value = hh/127^2 + xx/(127*32258)
// ===========================================================================
__global__ void finalize_kernel(float* __restrict__ out) {
    const int idx = blockIdx.x * blockDim.x + threadIdx.x;
    if (idx >= BATCH * CH * CH) return;
    const int b  = idx >> 14;
    const int ij = idx & 16383;
    const int i  = ij >> 7;
    const int j  = ij & 127;
    int hhre = 0, xxre = 0, hhim = 0, xxim = 0;
#pragma unroll
    for (int ks = 0; ks < KSPLIT; ks++) {
        const int2* __restrict__ base =
            g_gram + ((size_t)((ks * BATCH + b) * 3)) * (CH * CH);
        int2 g0 = base[ij];
        int2 g1 = base[CH * CH + ij];
        int2 g2 = base[2 * CH * CH + i * CH + j];
        int2 g2t = base[2 * CH * CH + j * CH + i];
        hhre += g0.x + g1.x;  xxre += g0.y + g1.y;
        hhim += g2.x - g2t.x; xxim += g2.y - g2t.y;
    }
    const float c1 = 1.0f / 16129.0f;        // 1/127^2
    const float c2 = 1.0f / 4096766.0f;      // 1/(127*32258)
    float re = (float)hhre * c1 + (float)xxre * c2;
    float im = (float)hhim * c1 + (float)xxim * c2;
    out[idx] = sqrtf(re * re + im * im) * (1.0f / (float)T_LEN);
}

// ===========================================================================
extern "C" void kernel_launch(void* const* d_in, const int* in_sizes, int n_in,
                              void* d_out, int out_size) {
    const float* x = (const float*)d_in[0];
    float* out = (float*)d_out;

    const int fft_smem = (T_LEN + HALF) * (int)sizeof(float2);  // 96 KB
    cudaFuncSetAttribute(fft_kernel, cudaFuncAttributeMaxDynamicSharedMemorySize,
                         fft_smem);
    cudaFuncSetAttribute(gram_s8, cudaFuncAttributeMaxDynamicSharedMemorySize,
                         2 * BUFB);

    fft_kernel<<<NSIG, 512, fft_smem>>>(x);
    gram_s8<<<dim3(KSPLIT, 6, BATCH), 256, 2 * BUFB>>>();
    finalize_kernel<<<(BATCH * CH * CH + 255) / 256, 256>>>(out);
}

// round 11
// speedup vs baseline: 1.6375x; 1.6375x over previous
#include <cuda_runtime.h>
#include <math.h>
#include <stdint.h>

#define T_LEN 8192
#define HALF  4096
#define CH    128
#define BATCH 16
#define NSIG  (BATCH * CH)

#define KSPLIT 16
#define KC     32                          // fp32 per chunk = 128 B rows
#define NCHUNK ((T_LEN / KSPLIT) / KC)     // 16
#define ROWB   144                         // 128B data + 16B pad (conflict-free)
#define BOFF   (128 * ROWB)                // 18432
#define BUFB   (2 * 128 * ROWB)            // 36864 per buffer

// Scratch (alloc-free rule: __device__ globals)
__device__ float g_c[(size_t)BATCH * CH * T_LEN];             // cos(phase): 64 MB
__device__ float g_s[(size_t)BATCH * CH * T_LEN];             // sin(phase): 64 MB
__device__ float g_gram[(size_t)KSPLIT * BATCH * 3 * CH * CH];// tiles: 50 MB

// ===========================================================================
// PTX helpers
// ===========================================================================
__device__ __forceinline__ uint32_t smem_u32(const void* p) {
    uint32_t a;
    asm("{ .reg .u64 t; cvta.to.shared.u64 t, %1; cvt.u32.u64 %0, t; }"
        : "=r"(a) : "l"(p));
    return a;
}
__device__ __forceinline__ void mma_tf32(float* d, const uint32_t* a,
                                         const uint32_t* b) {
    asm volatile(
        "mma.sync.aligned.m16n8k8.row.col.f32.tf32.tf32.f32 "
        "{%0,%1,%2,%3}, {%4,%5,%6,%7}, {%8,%9}, {%0,%1,%2,%3};"
        : "+f"(d[0]), "+f"(d[1]), "+f"(d[2]), "+f"(d[3])
        : "r"(a[0]), "r"(a[1]), "r"(a[2]), "r"(a[3]), "r"(b[0]), "r"(b[1]));
}
__device__ __forceinline__ void cp16(uint32_t smem, const void* g) {
    asm volatile("cp.async.cg.shared.global [%0], [%1], 16;"
                 :: "r"(smem), "l"(g) : "memory");
}
#define CP_COMMIT() asm volatile("cp.async.commit_group;" ::: "memory")
#define CP_WAIT1()  asm volatile("cp.async.wait_group 1;" ::: "memory")
#define CP_WAIT0()  asm volatile("cp.async.wait_group 0;" ::: "memory")
__device__ __forceinline__ uint32_t lds32(uint32_t addr) {
    uint32_t v;
    asm volatile("ld.shared.b32 %0, [%1];" : "=r"(v) : "r"(addr));
    return v;
}
__device__ __forceinline__ uint32_t f2tf32(float f) {
    uint32_t u;
    asm("cvt.rna.tf32.f32 %0, %1;" : "=r"(u) : "f"(f));
    return u;
}

// ===========================================================================
// Kernel 1: register-resident FFT (R9 body, twiddle hoisting), direct tf32
// epilogue: cvt.rna once, coalesced STG.32.
// ===========================================================================
__device__ __forceinline__ int swz(int i) { return i ^ ((i >> 5) & 31); }

template<int P, int LB, int FWD>
__device__ __forceinline__ void stage_one(float2 v[16], int base,
                                          const float2* __restrict__ tw) {
    const int s  = P + LB;
    const int bm = base & ((1 << s) - 1);
    float2 wc[(LB < 3) ? (1 << LB) : 1];
    if (LB < 3) {
#pragma unroll
        for (int q = 0; q < (1 << LB); q++)
            wc[q] = tw[(bm + (q << P)) << (12 - s)];
    }
#pragma unroll
    for (int rr = 0; rr < 16; rr++) {
        if ((rr >> LB) & 1) continue;
        const int r1 = rr | (1 << LB);
        float2 w;
        if (LB < 3) w = wc[rr & ((1 << LB) - 1)];
        else        w = tw[(bm + ((rr & 7) << P)) << (12 - s)];
        float2 a = v[rr], b = v[r1];
        if (FWD) {
            v[rr] = make_float2(a.x + b.x, a.y + b.y);
            float2 d = make_float2(a.x - b.x, a.y - b.y);
            v[r1] = make_float2(d.x * w.x - d.y * w.y, d.x * w.y + d.y * w.x);
        } else {
            float2 tt = make_float2(b.x * w.x + b.y * w.y, b.y * w.x - b.x * w.y);
            v[rr] = make_float2(a.x + tt.x, a.y + tt.y);
            v[r1] = make_float2(a.x - tt.x, a.y - tt.y);
        }
    }
}

template<int P, int FWD, int LBLO, int LBHI>
__device__ __forceinline__ void stages(float2 v[16], int base,
                                       const float2* __restrict__ tw) {
    if (FWD) {
        if (LBHI >= 3 && 3 >= LBLO) stage_one<P, 3, 1>(v, base, tw);
        if (LBHI >= 2 && 2 >= LBLO) stage_one<P, 2, 1>(v, base, tw);
        if (LBHI >= 1 && 1 >= LBLO) stage_one<P, 1, 1>(v, base, tw);
        if (LBHI >= 0 && 0 >= LBLO) stage_one<P, 0, 1>(v, base, tw);
    } else {
        if (LBLO <= 0 && 0 <= LBHI) stage_one<P, 0, 0>(v, base, tw);
        if (LBLO <= 1 && 1 <= LBHI) stage_one<P, 1, 0>(v, base, tw);
        if (LBLO <= 2 && 2 <= LBHI) stage_one<P, 2, 0>(v, base, tw);
        if (LBLO <= 3 && 3 <= LBHI) stage_one<P, 3, 0>(v, base, tw);
    }
}

extern __shared__ float2 smm[];   // [0..8191]=exchange, [8192..12287]=twiddles

__global__ void __launch_bounds__(512) fft_kernel(const float* __restrict__ x) {
    float2* sm = smm;
    float2* tw = smm + T_LEN;
    const int tid = threadIdx.x;
    const long long gbase = (long long)blockIdx.x * T_LEN;

    for (int t = tid; t < HALF; t += 512) {
        float s, c;
        sincosf(-6.283185307179586e0f * (float)t / (float)T_LEN, &s, &c);
        tw[t] = make_float2(c, s);
    }

    const int baseA = tid;                                  // P=9
    const int baseB = ((tid >> 5) << 9) + (tid & 31);       // P=5
    const int baseC = ((tid >> 1) << 5) + (tid & 1);        // P=1
    const int baseD = tid << 4;                             // P=0
    const int baseE = ((tid >> 4) << 8) + (tid & 15);       // P=4
    const int baseF = ((tid >> 8) << 12) + (tid & 255);     // P=8

    float2 v[16];
#pragma unroll
    for (int r = 0; r < 16; r++)
        v[r] = make_float2(x[gbase + tid + r * 512], 0.0f);
    __syncthreads();

    stages<9, 1, 0, 3>(v, baseA, tw);
#pragma unroll
    for (int r = 0; r < 16; r++) sm[swz(baseA + (r << 9))] = v[r];
    __syncthreads();
#pragma unroll
    for (int r = 0; r < 16; r++) v[r] = sm[swz(baseB + (r << 5))];
    __syncthreads();

    stages<5, 1, 0, 3>(v, baseB, tw);
#pragma unroll
    for (int r = 0; r < 16; r++) sm[swz(baseB + (r << 5))] = v[r];
    __syncthreads();
#pragma unroll
    for (int r = 0; r < 16; r++) v[r] = sm[swz(baseC + (r << 1))];
    __syncthreads();

    stages<1, 1, 0, 3>(v, baseC, tw);
#pragma unroll
    for (int r = 0; r < 16; r++) sm[swz(baseC + (r << 1))] = v[r];
    __syncthreads();
#pragma unroll
    for (int r = 0; r < 16; r++) v[r] = sm[swz(baseD + r)];
    __syncthreads();

#pragma unroll
    for (int r = 0; r < 16; r += 2) {
        float2 s0 = make_float2(v[r].x + v[r + 1].x, v[r].y + v[r + 1].y);
        v[r] = s0; v[r + 1] = s0;
    }

    stages<0, 0, 1, 3>(v, baseD, tw);
#pragma unroll
    for (int r = 0; r < 16; r++) sm[swz(baseD + r)] = v[r];
    __syncthreads();
#pragma unroll
    for (int r = 0; r < 16; r++) v[r] = sm[swz(baseE + (r << 4))];
    __syncthreads();

    stages<4, 0, 0, 3>(v, baseE, tw);
#pragma unroll
    for (int r = 0; r < 16; r++) sm[swz(baseE + (r << 4))] = v[r];
    __syncthreads();
#pragma unroll
    for (int r = 0; r < 16; r++) v[r] = sm[swz(baseF + (r << 8))];
    __syncthreads();

    stages<8, 0, 0, 3>(v, baseF, tw);
#pragma unroll
    for (int r = 0; r < 16; r++) sm[swz(baseF + (r << 8))] = v[r];
    __syncthreads();
#pragma unroll
    for (int r = 0; r < 16; r++) v[r] = sm[swz(baseA + (r << 9))];
    __syncthreads();

    stages<9, 0, 3, 3>(v, baseA, tw);

    // ---- epilogue: normalize, round to tf32, direct coalesced stores ----
    const size_t rowb = (size_t)blockIdx.x * T_LEN;
#pragma unroll
    for (int r = 0; r < 16; r++) {
        const int t = tid + r * 512;
        float2 u = v[r];
        float m2 = u.x * u.x + u.y * u.y;
        float cx, sx;
        if (m2 > 0.0f) {
            float inv = rsqrtf(m2);
            cx = u.x * inv; sx = u.y * inv;
        } else {
            cx = 1.0f; sx = 0.0f;
        }
        g_c[rowb + t] = __uint_as_float(f2tf32(cx));
        g_s[rowb + t] = __uint_as_float(f2tf32(sx));
    }
}

// ===========================================================================
// Kernel 2: tf32 single-chain Gram via mma.sync.m16n8k8.
// CTA = (ks, q, b). q: 0=CC (A=B=cos), 1=SS (A=B=sin), 2=SC (A=sin, B=cos).
// Diagonal tiles alias B into A's smem region (half the loads).
// ===========================================================================
extern __shared__ __align__(128) char gsm[];   // 2 * BUFB = 73728 B

__global__ void __launch_bounds__(256, 2) gram_tf32() {
    const int tid  = threadIdx.x;
    const int wid  = tid >> 5;
    const int lane = tid & 31;
    const int ks   = blockIdx.x;
    const int q    = blockIdx.y;
    const int b    = blockIdx.z;
    const bool diag = (q < 2);

    const float* __restrict__ srcA = (q == 0) ? g_c : g_s;
    const float* __restrict__ srcB = (q == 1) ? g_s : g_c;

    const uint32_t sb = smem_u32(gsm);
    const size_t k0 = (size_t)ks * (T_LEN / KSPLIT);

    // ---- loader: pass p covers 32 rows; A passes 0-3, B passes 4-7 ----
    const int qi  = tid & 7;                  // 16B quad within 128B row
    const int r32 = tid >> 3;                 // 0..31
    const int npass = diag ? 4 : 8;

    const float* psrc[8]; uint32_t pdst[8];
#pragma unroll
    for (int p = 0; p < 8; p++) {
        const int row = r32 + (p & 3) * 32;
        const float* srcm = (p < 4) ? srcA : srcB;
        psrc[p] = srcm + (size_t)(b * CH + row) * T_LEN + k0 + qi * 4;
        pdst[p] = (uint32_t)((p < 4 ? 0 : BOFF) + row * ROWB + qi * 16);
    }

    auto load_chunk = [&](int c) {
        const uint32_t bufb = sb + (uint32_t)((c & 1) * BUFB);
        const int kofs = c * KC;
#pragma unroll
        for (int p = 0; p < 8; p++) {
            if (p >= npass) break;
            cp16(bufb + pdst[p], psrc[p] + kofs);
        }
        CP_COMMIT();
    };

    // ---- compute: 8 warps = 2m x 4n; warp tile 64x32 ----
    const int mrow0 = (wid >> 2) * 64;
    const int ncol0 = (wid & 3) * 32;
    const uint32_t bOfs = diag ? 0u : (uint32_t)BOFF;

    float acc[4][4][4];
#pragma unroll
    for (int mt = 0; mt < 4; mt++)
#pragma unroll
        for (int nt = 0; nt < 4; nt++)
#pragma unroll
            for (int e = 0; e < 4; e++) acc[mt][nt][e] = 0.0f;

    const int lg = lane >> 2;                 // 0..7 (row/col group)
    const int lk = lane & 3;                  // 0..3 (k within half-tile)

    load_chunk(0);
    for (int c = 0; c < NCHUNK; c++) {
        if (c + 1 < NCHUNK) { load_chunk(c + 1); CP_WAIT1(); }
        else                { CP_WAIT0(); }
        __syncthreads();

        const uint32_t bufb = sb + (uint32_t)((c & 1) * BUFB);
#pragma unroll
        for (int kstep = 0; kstep < KC / 8; kstep++) {
            const uint32_t kb = (uint32_t)(kstep * 32 + lk * 4);
            // B fragments for all 4 nt (2 regs each)
            uint32_t bfr[4][2];
#pragma unroll
            for (int nt = 0; nt < 4; nt++) {
                const uint32_t ba =
                    bufb + bOfs + (uint32_t)((ncol0 + nt * 8 + lg) * ROWB) + kb;
                bfr[nt][0] = lds32(ba);
                bfr[nt][1] = lds32(ba + 16);
            }
#pragma unroll
            for (int mt = 0; mt < 4; mt++) {
                const uint32_t aa =
                    bufb + (uint32_t)((mrow0 + mt * 16 + lg) * ROWB) + kb;
                uint32_t af[4];
                af[0] = lds32(aa);
                af[1] = lds32(aa + 8 * ROWB);
                af[2] = lds32(aa + 16);
                af[3] = lds32(aa + 8 * ROWB + 16);
#pragma unroll
                for (int nt = 0; nt < 4; nt++)
                    mma_tf32(acc[mt][nt], af, bfr[nt]);
            }
        }
        __syncthreads();
    }

    // ---- epilogue ----
    float* __restrict__ G =
        g_gram + ((size_t)((ks * BATCH + b) * 3 + q)) * (CH * CH);
    const int r0 = lane >> 2;
    const int c0 = (lane & 3) * 2;
#pragma unroll
    for (int mt = 0; mt < 4; mt++) {
        const int row = mrow0 + mt * 16 + r0;
#pragma unroll
        for (int nt = 0; nt < 4; nt++) {
            const int col = ncol0 + nt * 8 + c0;
            *(float2*)(G + row * CH + col) =
                make_float2(acc[mt][nt][0], acc[mt][nt][1]);
            *(float2*)(G + (row + 8) * CH + col) =
                make_float2(acc[mt][nt][2], acc[mt][nt][3]);
        }
    }
}

// ===========================================================================
// Kernel 3: combine K-splits; Re = CC+SS, Im = SC_ij - SC_ji; PLV = |.|/T.
// ===========================================================================
__global__ void finalize_kernel(float* __restrict__ out) {
    const int idx = blockIdx.x * blockDim.x + threadIdx.x;
    if (idx >= BATCH * CH * CH) return;
    const int b  = idx >> 14;
    const int ij = idx & 16383;
    const int i  = ij >> 7;
    const int j  = ij & 127;
    float re = 0.0f, im = 0.0f;
#pragma unroll
    for (int ks = 0; ks < KSPLIT; ks++) {
        const float* __restrict__ base =
            g_gram + ((size_t)((ks * BATCH + b) * 3)) * (CH * CH);
        re += base[ij] + base[CH * CH + ij];                       // CC + SS
        im += base[2 * CH * CH + i * CH + j]
            - base[2 * CH * CH + j * CH + i];                      // SC - SC^T
    }
    out[idx] = sqrtf(re * re + im * im) * (1.0f / (float)T_LEN);
}

// ===========================================================================
extern "C" void kernel_launch(void* const* d_in, const int* in_sizes, int n_in,
                              void* d_out, int out_size) {
    const float* x = (const float*)d_in[0];
    float* out = (float*)d_out;

    const int fft_smem = (T_LEN + HALF) * (int)sizeof(float2);  // 96 KB
    cudaFuncSetAttribute(fft_kernel, cudaFuncAttributeMaxDynamicSharedMemorySize,
                         fft_smem);
    cudaFuncSetAttribute(gram_tf32, cudaFuncAttributeMaxDynamicSharedMemorySize,
                         2 * BUFB);

    fft_kernel<<<NSIG, 512, fft_smem>>>(x);
    gram_tf32<<<dim3(KSPLIT, 3, BATCH), 256, 2 * BUFB>>>();
    finalize_kernel<<<(BATCH * CH * CH + 255) / 256, 256>>>(out);
}